// round 5
// baseline (speedup 1.0000x reference)
#include <cuda_runtime.h>

#define BB 2
#define NN 256
#define DD 128
#define RR 32
#define JT 16
#define NTILES (NN / JT)
#define TPB 256
#define SSTRIDE 68   // floats per e-row in sh_s: 16 j * 4 k + 4 pad (16B-aligned)

typedef unsigned long long ull;

// scratch for h = node_s @ src_w  (B*N*D floats)
__device__ float g_h[BB * NN * DD];

// ---------------------------------------------------------------------------
// packed f32x2 helpers
// ---------------------------------------------------------------------------
__device__ __forceinline__ ull pack2(float lo, float hi) {
    ull r;
    asm("mov.b64 %0, {%1, %2};" : "=l"(r) : "f"(lo), "f"(hi));
    return r;
}
__device__ __forceinline__ float2 unpack2(ull v) {
    float2 f;
    asm("mov.b64 {%0, %1}, %2;" : "=f"(f.x), "=f"(f.y) : "l"(v));
    return f;
}
__device__ __forceinline__ ull fma2(ull a, ull b, ull c) {
    ull d;
    asm("fma.rn.f32x2 %0, %1, %2, %3;" : "=l"(d) : "l"(a), "l"(b), "l"(c));
    return d;
}
__device__ __forceinline__ float silu(float x) {
    return x / (1.0f + __expf(-x));
}

// ---------------------------------------------------------------------------
// Kernel 1: h[b,n,d] = node_s[b,n,:] @ src_w[:,d]
// ---------------------------------------------------------------------------
__global__ void __launch_bounds__(DD) compute_h_kernel(
    const float* __restrict__ node_s,
    const float* __restrict__ src_w) {
    __shared__ float sh[DD];
    int row = blockIdx.x;
    int d = threadIdx.x;
    sh[d] = node_s[row * DD + d];
    __syncthreads();
    float acc = 0.0f;
#pragma unroll 8
    for (int k = 0; k < DD; ++k)
        acc = fmaf(sh[k], src_w[k * DD + d], acc);
    g_h[row * DD + d] = acc;
}

// ---------------------------------------------------------------------------
// Kernel 2: fused message block. One CTA per (b,i); 256 threads:
//   thread t -> (lane = t&127, j-half = t>>7). Each j-half team of 128
//   threads handles 8 of the 16 j's per tile.
// ---------------------------------------------------------------------------
__global__ void __launch_bounds__(TPB, 3) se3_main_kernel(
    const float* __restrict__ node_v,
    const float* __restrict__ rbf,
    const float* __restrict__ r_hat,
    const float* __restrict__ mask,
    const float* __restrict__ w1_0, const float* __restrict__ b1_0,
    const float* __restrict__ w2_0, const float* __restrict__ b2_0,
    const float* __restrict__ w1_1, const float* __restrict__ b1_1,
    const float* __restrict__ w2_1, const float* __restrict__ b2_1,
    const float* __restrict__ w1_2, const float* __restrict__ b1_2,
    const float* __restrict__ w2_2, const float* __restrict__ b2_2,
    const float* __restrict__ w1_3, const float* __restrict__ b1_3,
    const float* __restrict__ w2_3, const float* __restrict__ b2_3,
    const float* __restrict__ ln_g, const float* __restrict__ ln_b,
    const float* __restrict__ out_w, const float* __restrict__ out_b,
    const float* __restrict__ v_scale, const float* __restrict__ t_scale,
    float* __restrict__ out) {

    __shared__ float sh_s[DD * SSTRIDE];     // [e][j][k0..3] (+pad)
    __shared__ float sh_rbfT[RR][JT];        // [r][j]
    __shared__ float sh_Y1[3][JT];
    __shared__ float sh_Y2[5][JT];
    __shared__ float sh_mask[JT];
    __shared__ float sh_part[10][DD];        // second-half partial accumulators
    __shared__ float sh_red[DD];
    __shared__ float sh_r1[4], sh_r2[4];

    const int tid   = threadIdx.x;
    const int lane  = tid & (DD - 1);        // = e in phase1, = d in phase2
    const int jh    = tid >> 7;              // 0 or 1
    const int jbase = jh * 8;
    const int bi    = blockIdx.x;
    const int b     = bi >> 8;
    const long long edge_base = (long long)bi * NN;

    const float* W1[4] = {w1_0, w1_1, w1_2, w1_3};
    const float* W2[4] = {w2_0, w2_1, w2_2, w2_3};

    float b1r[4];
    b1r[0] = b1_0[lane]; b1r[1] = b1_1[lane];
    b1r[2] = b1_2[lane]; b1r[3] = b1_3[lane];
    const ull bA = pack2(b2_0[lane], b2_1[lane]);   // branch pair (0,1)
    const ull bB = pack2(b2_2[lane], b2_3[lane]);   // branch pair (2,3)

    float vreg[3];
#pragma unroll
    for (int c = 0; c < 3; ++c)
        vreg[c] = node_v[((long long)bi * 3 + c) * DD + lane];

    float accS = 0.0f, accSV = 0.0f;
    float accV[3] = {0.0f, 0.0f, 0.0f};
    float accT[5] = {0.0f, 0.0f, 0.0f, 0.0f, 0.0f};

    for (int t = 0; t < NTILES; ++t) {
        const int j0 = t * JT;

        // ---- stage rbf (transposed), mask, Y1, Y2 ----
        for (int idx = tid; idx < JT * RR; idx += TPB) {
            int j = idx >> 5, r = idx & 31;
            sh_rbfT[r][j] = rbf[(edge_base + j0 + j) * RR + r];
        }
        if (tid < JT) {
            int j = tid;
            long long e = edge_base + j0 + j;
            sh_mask[j] = mask[e];
            float x = r_hat[e * 3 + 0];
            float y = r_hat[e * 3 + 1];
            float z = r_hat[e * 3 + 2];
            const float s3  = 1.7320508075688772f;
            const float c15 = 3.872983346207417f;
            const float c5h = 1.118033988749895f;
            sh_Y1[0][j] = s3 * x;
            sh_Y1[1][j] = s3 * y;
            sh_Y1[2][j] = s3 * z;
            sh_Y2[0][j] = c15 * x * y;
            sh_Y2[1][j] = c15 * y * z;
            sh_Y2[2][j] = c5h * (3.0f * z * z - 1.0f);
            sh_Y2[3][j] = c15 * x * z;
            sh_Y2[4][j] = 0.5f * c15 * (x * x - y * y);
        }
        __syncthreads();

        // ---- phase 1: hidden layer + SiLU. e = lane, 8 j's of this half ----
        {
            const int e = lane;
            ull h1[4][4];   // [k][j-pair]
#pragma unroll
            for (int k = 0; k < 4; ++k) {
                ull bd = pack2(b1r[k], b1r[k]);
#pragma unroll
                for (int p = 0; p < 4; ++p) h1[k][p] = bd;
            }
#pragma unroll 4
            for (int r = 0; r < RR; ++r) {
                const float4* rb4 =
                    reinterpret_cast<const float4*>(&sh_rbfT[r][jbase]);
                float4 f0 = rb4[0], f1 = rb4[1];
                ull r01 = pack2(f0.x, f0.y), r23 = pack2(f0.z, f0.w);
                ull r45 = pack2(f1.x, f1.y), r67 = pack2(f1.z, f1.w);
#pragma unroll
                for (int k = 0; k < 4; ++k) {
                    float w = W1[k][r * DD + e];
                    ull wd = pack2(w, w);
                    h1[k][0] = fma2(r01, wd, h1[k][0]);
                    h1[k][1] = fma2(r23, wd, h1[k][1]);
                    h1[k][2] = fma2(r45, wd, h1[k][2]);
                    h1[k][3] = fma2(r67, wd, h1[k][3]);
                }
            }
            float* srow = &sh_s[e * SSTRIDE];
#pragma unroll
            for (int p = 0; p < 4; ++p) {
                float2 v0 = unpack2(h1[0][p]);
                float2 v1 = unpack2(h1[1][p]);
                float2 v2 = unpack2(h1[2][p]);
                float2 v3 = unpack2(h1[3][p]);
                float4 se = make_float4(silu(v0.x), silu(v1.x), silu(v2.x), silu(v3.x));
                float4 so = make_float4(silu(v0.y), silu(v1.y), silu(v2.y), silu(v3.y));
                *reinterpret_cast<float4*>(&srow[(jbase + 2 * p) * 4])     = se;
                *reinterpret_cast<float4*>(&srow[(jbase + 2 * p + 1) * 4]) = so;
            }
        }
        __syncthreads();

        // ---- phase 2: second linear layer. d = lane, 8 j's of this half ----
        ull accA[8], accB[8];   // per j: (k0,k1) and (k2,k3) packed
#pragma unroll
        for (int j = 0; j < 8; ++j) { accA[j] = bA; accB[j] = bB; }

#pragma unroll 2
        for (int e = 0; e < DD; ++e) {
            float w0  = W2[0][e * DD + lane];
            float w1v = W2[1][e * DD + lane];
            float w2v = W2[2][e * DD + lane];
            float w3v = W2[3][e * DD + lane];
            ull wA = pack2(w0, w1v);
            ull wB = pack2(w2v, w3v);
            const float4* sp =
                reinterpret_cast<const float4*>(&sh_s[e * SSTRIDE + jbase * 4]);
#pragma unroll
            for (int j = 0; j < 8; ++j) {
                float4 sv = sp[j];                 // (k0,k1,k2,k3) for this (e,j)
                accA[j] = fma2(pack2(sv.x, sv.y), wA, accA[j]);
                accB[j] = fma2(pack2(sv.z, sv.w), wB, accB[j]);
            }
        }

        // ---- epilogue: fold mask, h_j, Y into running sums ----
#pragma unroll
        for (int j = 0; j < 8; ++j) {
            int jj = jbase + j;
            float2 rAB = unpack2(accA[j]);   // r0, r1
            float2 rCD = unpack2(accB[j]);   // r2, r3
            float m  = sh_mask[jj];
            float hj = g_h[((long long)b * NN + (j0 + jj)) * DD + lane];
            float mh = m * hj;
            accS = fmaf(mh, rAB.x, accS);
            float t1 = mh * rAB.y;
            float y10 = sh_Y1[0][jj], y11 = sh_Y1[1][jj], y12 = sh_Y1[2][jj];
            accV[0] = fmaf(t1, y10, accV[0]);
            accV[1] = fmaf(t1, y11, accV[1]);
            accV[2] = fmaf(t1, y12, accV[2]);
            float t2 = mh * rCD.x;
#pragma unroll
            for (int c = 0; c < 5; ++c)
                accT[c] = fmaf(t2, sh_Y2[c][jj], accT[c]);
            float dv = vreg[0] * y10 + vreg[1] * y11 + vreg[2] * y12;
            accSV = fmaf(m * dv, rCD.y, accSV);
        }
        __syncthreads();
    }

    // ---- combine the two j-half teams ----
    if (jh == 1) {
        sh_part[0][lane] = accS;
        sh_part[1][lane] = accV[0];
        sh_part[2][lane] = accV[1];
        sh_part[3][lane] = accV[2];
        sh_part[4][lane] = accT[0];
        sh_part[5][lane] = accT[1];
        sh_part[6][lane] = accT[2];
        sh_part[7][lane] = accT[3];
        sh_part[8][lane] = accT[4];
        sh_part[9][lane] = accSV;
    }
    __syncthreads();

    if (jh == 0) {
        accS    += sh_part[0][lane];
        accV[0] += sh_part[1][lane];
        accV[1] += sh_part[2][lane];
        accV[2] += sh_part[3][lane];
        accT[0] += sh_part[4][lane];
        accT[1] += sh_part[5][lane];
        accT[2] += sh_part[6][lane];
        accT[3] += sh_part[7][lane];
        accT[4] += sh_part[8][lane];
        accSV   += sh_part[9][lane];

        float x = accS + accSV;
        float s1 = x, s2 = x * x;
#pragma unroll
        for (int o = 16; o > 0; o >>= 1) {
            s1 += __shfl_xor_sync(0xffffffff, s1, o);
            s2 += __shfl_xor_sync(0xffffffff, s2, o);
        }
        if ((lane & 31) == 0) {
            sh_r1[lane >> 5] = s1;
            sh_r2[lane >> 5] = s2;
        }
    }
    __syncthreads();

    if (jh == 0) {
        float x = accS + accSV;
        float s1 = sh_r1[0] + sh_r1[1] + sh_r1[2] + sh_r1[3];
        float s2 = sh_r2[0] + sh_r2[1] + sh_r2[2] + sh_r2[3];
        float mean = s1 * (1.0f / DD);
        float var  = s2 * (1.0f / DD) - mean * mean;
        float nv = (x - mean) * rsqrtf(var + 1e-5f) * ln_g[lane] + ln_b[lane];
        sh_red[lane] = nv;
    }
    __syncthreads();

    if (jh == 0) {
        float y = out_b[lane];
#pragma unroll 8
        for (int e = 0; e < DD; ++e)
            y = fmaf(sh_red[e], out_w[e * DD + lane], y);

        const long long VOFF = (long long)BB * NN * DD;
        const long long TOFF = VOFF + (long long)BB * NN * 3 * DD;

        out[(long long)bi * DD + lane] = y;
        float vs = v_scale[lane];
#pragma unroll
        for (int c = 0; c < 3; ++c)
            out[VOFF + ((long long)bi * 3 + c) * DD + lane] = accV[c] * vs;
        float ts = t_scale[lane];
#pragma unroll
        for (int c = 0; c < 5; ++c)
            out[TOFF + ((long long)bi * 5 + c) * DD + lane] = accT[c] * ts;
    }
}

// ---------------------------------------------------------------------------
// kernel_launch
// ---------------------------------------------------------------------------
extern "C" void kernel_launch(void* const* d_in, const int* in_sizes, int n_in,
                              void* d_out, int out_size) {
    const float* node_s  = (const float*)d_in[0];
    const float* node_v  = (const float*)d_in[1];
    const float* rbf     = (const float*)d_in[3];
    const float* r_hat   = (const float*)d_in[4];
    const float* mask    = (const float*)d_in[5];
    const float* r0_w1   = (const float*)d_in[6];
    const float* r0_b1   = (const float*)d_in[7];
    const float* r0_w2   = (const float*)d_in[8];
    const float* r0_b2   = (const float*)d_in[9];
    const float* r1_w1   = (const float*)d_in[10];
    const float* r1_b1   = (const float*)d_in[11];
    const float* r1_w2   = (const float*)d_in[12];
    const float* r1_b2   = (const float*)d_in[13];
    const float* r2_w1   = (const float*)d_in[14];
    const float* r2_b1   = (const float*)d_in[15];
    const float* r2_w2   = (const float*)d_in[16];
    const float* r2_b2   = (const float*)d_in[17];
    const float* r110_w1 = (const float*)d_in[18];
    const float* r110_b1 = (const float*)d_in[19];
    const float* r110_w2 = (const float*)d_in[20];
    const float* r110_b2 = (const float*)d_in[21];
    const float* src_w   = (const float*)d_in[22];
    const float* ln_g    = (const float*)d_in[23];
    const float* ln_b    = (const float*)d_in[24];
    const float* out_w   = (const float*)d_in[25];
    const float* out_b   = (const float*)d_in[26];
    const float* v_scale = (const float*)d_in[27];
    const float* t_scale = (const float*)d_in[28];

    float* out = (float*)d_out;

    compute_h_kernel<<<BB * NN, DD>>>(node_s, src_w);
    se3_main_kernel<<<BB * NN, TPB>>>(
        node_v, rbf, r_hat, mask,
        r0_w1, r0_b1, r0_w2, r0_b2,
        r1_w1, r1_b1, r1_w2, r1_b2,
        r2_w1, r2_b1, r2_w2, r2_b2,
        r110_w1, r110_b1, r110_w2, r110_b2,
        ln_g, ln_b, out_w, out_b, v_scale, t_scale, out);
}

// round 6
// speedup vs baseline: 1.0001x; 1.0001x over previous
#include <cuda_runtime.h>

#define BB 2
#define NN 256
#define DD 128
#define RR 32
#define JT 16
#define NTILES (NN / JT)
#define TPB 256
#define SSTRIDE 68   // floats per e-row in sh_s: 16 j * 4 k + 4 pad (16B-aligned)

typedef unsigned long long ull;

// scratch for h = node_s @ src_w  (B*N*D floats)
__device__ float g_h[BB * NN * DD];

// ---------------------------------------------------------------------------
// packed f32x2 helpers
// ---------------------------------------------------------------------------
__device__ __forceinline__ ull pack2(float lo, float hi) {
    ull r;
    asm("mov.b64 %0, {%1, %2};" : "=l"(r) : "f"(lo), "f"(hi));
    return r;
}
__device__ __forceinline__ float2 unpack2(ull v) {
    float2 f;
    asm("mov.b64 {%0, %1}, %2;" : "=f"(f.x), "=f"(f.y) : "l"(v));
    return f;
}
__device__ __forceinline__ ull fma2(ull a, ull b, ull c) {
    ull d;
    asm("fma.rn.f32x2 %0, %1, %2, %3;" : "=l"(d) : "l"(a), "l"(b), "l"(c));
    return d;
}
__device__ __forceinline__ float silu(float x) {
    return x / (1.0f + __expf(-x));
}

// ---------------------------------------------------------------------------
// Kernel 1: h[b,n,d] = node_s[b,n,:] @ src_w[:,d]
// ---------------------------------------------------------------------------
__global__ void __launch_bounds__(DD) compute_h_kernel(
    const float* __restrict__ node_s,
    const float* __restrict__ src_w) {
    __shared__ float sh[DD];
    int row = blockIdx.x;
    int d = threadIdx.x;
    sh[d] = node_s[row * DD + d];
    __syncthreads();
    float acc = 0.0f;
#pragma unroll 8
    for (int k = 0; k < DD; ++k)
        acc = fmaf(sh[k], src_w[k * DD + d], acc);
    g_h[row * DD + d] = acc;
}

// ---------------------------------------------------------------------------
// Kernel 2: fused message block. One CTA per (b,i); 256 threads:
//   thread t -> (lane = t&127, j-half = t>>7). Each j-half team of 128
//   threads handles 8 of the 16 j's per tile.
// ---------------------------------------------------------------------------
__global__ void __launch_bounds__(TPB, 3) se3_main_kernel(
    const float* __restrict__ node_v,
    const float* __restrict__ rbf,
    const float* __restrict__ r_hat,
    const float* __restrict__ mask,
    const float* __restrict__ w1_0, const float* __restrict__ b1_0,
    const float* __restrict__ w2_0, const float* __restrict__ b2_0,
    const float* __restrict__ w1_1, const float* __restrict__ b1_1,
    const float* __restrict__ w2_1, const float* __restrict__ b2_1,
    const float* __restrict__ w1_2, const float* __restrict__ b1_2,
    const float* __restrict__ w2_2, const float* __restrict__ b2_2,
    const float* __restrict__ w1_3, const float* __restrict__ b1_3,
    const float* __restrict__ w2_3, const float* __restrict__ b2_3,
    const float* __restrict__ ln_g, const float* __restrict__ ln_b,
    const float* __restrict__ out_w, const float* __restrict__ out_b,
    const float* __restrict__ v_scale, const float* __restrict__ t_scale,
    float* __restrict__ out) {

    __shared__ float sh_s[DD * SSTRIDE];     // [e][j][k0..3] (+pad)
    __shared__ float sh_rbfT[RR][JT];        // [r][j]
    __shared__ float sh_Y1[3][JT];
    __shared__ float sh_Y2[5][JT];
    __shared__ float sh_mask[JT];
    __shared__ float sh_part[10][DD];        // second-half partial accumulators
    __shared__ float sh_red[DD];
    __shared__ float sh_r1[4], sh_r2[4];

    const int tid   = threadIdx.x;
    const int lane  = tid & (DD - 1);        // = e in phase1, = d in phase2
    const int jh    = tid >> 7;              // 0 or 1
    const int jbase = jh * 8;
    const int bi    = blockIdx.x;
    const int b     = bi >> 8;
    const long long edge_base = (long long)bi * NN;

    const float* W1[4] = {w1_0, w1_1, w1_2, w1_3};
    const float* W2[4] = {w2_0, w2_1, w2_2, w2_3};

    float b1r[4];
    b1r[0] = b1_0[lane]; b1r[1] = b1_1[lane];
    b1r[2] = b1_2[lane]; b1r[3] = b1_3[lane];
    const ull bA = pack2(b2_0[lane], b2_1[lane]);   // branch pair (0,1)
    const ull bB = pack2(b2_2[lane], b2_3[lane]);   // branch pair (2,3)

    float vreg[3];
#pragma unroll
    for (int c = 0; c < 3; ++c)
        vreg[c] = node_v[((long long)bi * 3 + c) * DD + lane];

    float accS = 0.0f, accSV = 0.0f;
    float accV[3] = {0.0f, 0.0f, 0.0f};
    float accT[5] = {0.0f, 0.0f, 0.0f, 0.0f, 0.0f};

    for (int t = 0; t < NTILES; ++t) {
        const int j0 = t * JT;

        // ---- stage rbf (transposed), mask, Y1, Y2 ----
        for (int idx = tid; idx < JT * RR; idx += TPB) {
            int j = idx >> 5, r = idx & 31;
            sh_rbfT[r][j] = rbf[(edge_base + j0 + j) * RR + r];
        }
        if (tid < JT) {
            int j = tid;
            long long e = edge_base + j0 + j;
            sh_mask[j] = mask[e];
            float x = r_hat[e * 3 + 0];
            float y = r_hat[e * 3 + 1];
            float z = r_hat[e * 3 + 2];
            const float s3  = 1.7320508075688772f;
            const float c15 = 3.872983346207417f;
            const float c5h = 1.118033988749895f;
            sh_Y1[0][j] = s3 * x;
            sh_Y1[1][j] = s3 * y;
            sh_Y1[2][j] = s3 * z;
            sh_Y2[0][j] = c15 * x * y;
            sh_Y2[1][j] = c15 * y * z;
            sh_Y2[2][j] = c5h * (3.0f * z * z - 1.0f);
            sh_Y2[3][j] = c15 * x * z;
            sh_Y2[4][j] = 0.5f * c15 * (x * x - y * y);
        }
        __syncthreads();

        // ---- phase 1: hidden layer + SiLU. e = lane, 8 j's of this half ----
        {
            const int e = lane;
            ull h1[4][4];   // [k][j-pair]
#pragma unroll
            for (int k = 0; k < 4; ++k) {
                ull bd = pack2(b1r[k], b1r[k]);
#pragma unroll
                for (int p = 0; p < 4; ++p) h1[k][p] = bd;
            }
#pragma unroll 4
            for (int r = 0; r < RR; ++r) {
                const float4* rb4 =
                    reinterpret_cast<const float4*>(&sh_rbfT[r][jbase]);
                float4 f0 = rb4[0], f1 = rb4[1];
                ull r01 = pack2(f0.x, f0.y), r23 = pack2(f0.z, f0.w);
                ull r45 = pack2(f1.x, f1.y), r67 = pack2(f1.z, f1.w);
#pragma unroll
                for (int k = 0; k < 4; ++k) {
                    float w = W1[k][r * DD + e];
                    ull wd = pack2(w, w);
                    h1[k][0] = fma2(r01, wd, h1[k][0]);
                    h1[k][1] = fma2(r23, wd, h1[k][1]);
                    h1[k][2] = fma2(r45, wd, h1[k][2]);
                    h1[k][3] = fma2(r67, wd, h1[k][3]);
                }
            }
            float* srow = &sh_s[e * SSTRIDE];
#pragma unroll
            for (int p = 0; p < 4; ++p) {
                float2 v0 = unpack2(h1[0][p]);
                float2 v1 = unpack2(h1[1][p]);
                float2 v2 = unpack2(h1[2][p]);
                float2 v3 = unpack2(h1[3][p]);
                float4 se = make_float4(silu(v0.x), silu(v1.x), silu(v2.x), silu(v3.x));
                float4 so = make_float4(silu(v0.y), silu(v1.y), silu(v2.y), silu(v3.y));
                *reinterpret_cast<float4*>(&srow[(jbase + 2 * p) * 4])     = se;
                *reinterpret_cast<float4*>(&srow[(jbase + 2 * p + 1) * 4]) = so;
            }
        }
        __syncthreads();

        // ---- phase 2: second linear layer. d = lane, 8 j's of this half ----
        ull accA[8], accB[8];   // per j: (k0,k1) and (k2,k3) packed
#pragma unroll
        for (int j = 0; j < 8; ++j) { accA[j] = bA; accB[j] = bB; }

#pragma unroll 2
        for (int e = 0; e < DD; ++e) {
            float w0  = W2[0][e * DD + lane];
            float w1v = W2[1][e * DD + lane];
            float w2v = W2[2][e * DD + lane];
            float w3v = W2[3][e * DD + lane];
            ull wA = pack2(w0, w1v);
            ull wB = pack2(w2v, w3v);
            const float4* sp =
                reinterpret_cast<const float4*>(&sh_s[e * SSTRIDE + jbase * 4]);
#pragma unroll
            for (int j = 0; j < 8; ++j) {
                float4 sv = sp[j];                 // (k0,k1,k2,k3) for this (e,j)
                accA[j] = fma2(pack2(sv.x, sv.y), wA, accA[j]);
                accB[j] = fma2(pack2(sv.z, sv.w), wB, accB[j]);
            }
        }

        // ---- epilogue: fold mask, h_j, Y into running sums ----
#pragma unroll
        for (int j = 0; j < 8; ++j) {
            int jj = jbase + j;
            float2 rAB = unpack2(accA[j]);   // r0, r1
            float2 rCD = unpack2(accB[j]);   // r2, r3
            float m  = sh_mask[jj];
            float hj = g_h[((long long)b * NN + (j0 + jj)) * DD + lane];
            float mh = m * hj;
            accS = fmaf(mh, rAB.x, accS);
            float t1 = mh * rAB.y;
            float y10 = sh_Y1[0][jj], y11 = sh_Y1[1][jj], y12 = sh_Y1[2][jj];
            accV[0] = fmaf(t1, y10, accV[0]);
            accV[1] = fmaf(t1, y11, accV[1]);
            accV[2] = fmaf(t1, y12, accV[2]);
            float t2 = mh * rCD.x;
#pragma unroll
            for (int c = 0; c < 5; ++c)
                accT[c] = fmaf(t2, sh_Y2[c][jj], accT[c]);
            float dv = vreg[0] * y10 + vreg[1] * y11 + vreg[2] * y12;
            accSV = fmaf(m * dv, rCD.y, accSV);
        }
        __syncthreads();
    }

    // ---- combine the two j-half teams ----
    if (jh == 1) {
        sh_part[0][lane] = accS;
        sh_part[1][lane] = accV[0];
        sh_part[2][lane] = accV[1];
        sh_part[3][lane] = accV[2];
        sh_part[4][lane] = accT[0];
        sh_part[5][lane] = accT[1];
        sh_part[6][lane] = accT[2];
        sh_part[7][lane] = accT[3];
        sh_part[8][lane] = accT[4];
        sh_part[9][lane] = accSV;
    }
    __syncthreads();

    if (jh == 0) {
        accS    += sh_part[0][lane];
        accV[0] += sh_part[1][lane];
        accV[1] += sh_part[2][lane];
        accV[2] += sh_part[3][lane];
        accT[0] += sh_part[4][lane];
        accT[1] += sh_part[5][lane];
        accT[2] += sh_part[6][lane];
        accT[3] += sh_part[7][lane];
        accT[4] += sh_part[8][lane];
        accSV   += sh_part[9][lane];

        float x = accS + accSV;
        float s1 = x, s2 = x * x;
#pragma unroll
        for (int o = 16; o > 0; o >>= 1) {
            s1 += __shfl_xor_sync(0xffffffff, s1, o);
            s2 += __shfl_xor_sync(0xffffffff, s2, o);
        }
        if ((lane & 31) == 0) {
            sh_r1[lane >> 5] = s1;
            sh_r2[lane >> 5] = s2;
        }
    }
    __syncthreads();

    if (jh == 0) {
        float x = accS + accSV;
        float s1 = sh_r1[0] + sh_r1[1] + sh_r1[2] + sh_r1[3];
        float s2 = sh_r2[0] + sh_r2[1] + sh_r2[2] + sh_r2[3];
        float mean = s1 * (1.0f / DD);
        float var  = s2 * (1.0f / DD) - mean * mean;
        float nv = (x - mean) * rsqrtf(var + 1e-5f) * ln_g[lane] + ln_b[lane];
        sh_red[lane] = nv;
    }
    __syncthreads();

    if (jh == 0) {
        float y = out_b[lane];
#pragma unroll 8
        for (int e = 0; e < DD; ++e)
            y = fmaf(sh_red[e], out_w[e * DD + lane], y);

        const long long VOFF = (long long)BB * NN * DD;
        const long long TOFF = VOFF + (long long)BB * NN * 3 * DD;

        out[(long long)bi * DD + lane] = y;
        float vs = v_scale[lane];
#pragma unroll
        for (int c = 0; c < 3; ++c)
            out[VOFF + ((long long)bi * 3 + c) * DD + lane] = accV[c] * vs;
        float ts = t_scale[lane];
#pragma unroll
        for (int c = 0; c < 5; ++c)
            out[TOFF + ((long long)bi * 5 + c) * DD + lane] = accT[c] * ts;
    }
}

// ---------------------------------------------------------------------------
// kernel_launch
// ---------------------------------------------------------------------------
extern "C" void kernel_launch(void* const* d_in, const int* in_sizes, int n_in,
                              void* d_out, int out_size) {
    const float* node_s  = (const float*)d_in[0];
    const float* node_v  = (const float*)d_in[1];
    const float* rbf     = (const float*)d_in[3];
    const float* r_hat   = (const float*)d_in[4];
    const float* mask    = (const float*)d_in[5];
    const float* r0_w1   = (const float*)d_in[6];
    const float* r0_b1   = (const float*)d_in[7];
    const float* r0_w2   = (const float*)d_in[8];
    const float* r0_b2   = (const float*)d_in[9];
    const float* r1_w1   = (const float*)d_in[10];
    const float* r1_b1   = (const float*)d_in[11];
    const float* r1_w2   = (const float*)d_in[12];
    const float* r1_b2   = (const float*)d_in[13];
    const float* r2_w1   = (const float*)d_in[14];
    const float* r2_b1   = (const float*)d_in[15];
    const float* r2_w2   = (const float*)d_in[16];
    const float* r2_b2   = (const float*)d_in[17];
    const float* r110_w1 = (const float*)d_in[18];
    const float* r110_b1 = (const float*)d_in[19];
    const float* r110_w2 = (const float*)d_in[20];
    const float* r110_b2 = (const float*)d_in[21];
    const float* src_w   = (const float*)d_in[22];
    const float* ln_g    = (const float*)d_in[23];
    const float* ln_b    = (const float*)d_in[24];
    const float* out_w   = (const float*)d_in[25];
    const float* out_b   = (const float*)d_in[26];
    const float* v_scale = (const float*)d_in[27];
    const float* t_scale = (const float*)d_in[28];

    float* out = (float*)d_out;

    compute_h_kernel<<<BB * NN, DD>>>(node_s, src_w);
    se3_main_kernel<<<BB * NN, TPB>>>(
        node_v, rbf, r_hat, mask,
        r0_w1, r0_b1, r0_w2, r0_b2,
        r1_w1, r1_b1, r1_w2, r1_b2,
        r2_w1, r2_b1, r2_w2, r2_b2,
        r110_w1, r110_b1, r110_w2, r110_b2,
        ln_g, ln_b, out_w, out_b, v_scale, t_scale, out);
}

// round 7
// speedup vs baseline: 1.0005x; 1.0004x over previous
#include <cuda_runtime.h>

#define BB 2
#define NN 256
#define DD 128
#define RR 32
#define JT 16
#define NTILES (NN / JT)
#define TPB 256
#define SSTRIDE 68   // floats per e-row in sh_s: 16 j * 4 k + 4 pad (16B-aligned)

typedef unsigned long long ull;

// scratch for h = node_s @ src_w  (B*N*D floats)
__device__ float g_h[BB * NN * DD];

// ---------------------------------------------------------------------------
// packed f32x2 helpers
// ---------------------------------------------------------------------------
__device__ __forceinline__ ull pack2(float lo, float hi) {
    ull r;
    asm("mov.b64 %0, {%1, %2};" : "=l"(r) : "f"(lo), "f"(hi));
    return r;
}
__device__ __forceinline__ float2 unpack2(ull v) {
    float2 f;
    asm("mov.b64 {%0, %1}, %2;" : "=f"(f.x), "=f"(f.y) : "l"(v));
    return f;
}
__device__ __forceinline__ ull fma2(ull a, ull b, ull c) {
    ull d;
    asm("fma.rn.f32x2 %0, %1, %2, %3;" : "=l"(d) : "l"(a), "l"(b), "l"(c));
    return d;
}
__device__ __forceinline__ float silu(float x) {
    return x / (1.0f + __expf(-x));
}

// ---------------------------------------------------------------------------
// Kernel 1: h[b,n,d] = node_s[b,n,:] @ src_w[:,d]
// ---------------------------------------------------------------------------
__global__ void __launch_bounds__(DD) compute_h_kernel(
    const float* __restrict__ node_s,
    const float* __restrict__ src_w) {
    __shared__ float sh[DD];
    int row = blockIdx.x;
    int d = threadIdx.x;
    sh[d] = node_s[row * DD + d];
    __syncthreads();
    float acc = 0.0f;
#pragma unroll 8
    for (int k = 0; k < DD; ++k)
        acc = fmaf(sh[k], src_w[k * DD + d], acc);
    g_h[row * DD + d] = acc;
}

// ---------------------------------------------------------------------------
// Kernel 2: fused message block. One CTA per (b,i); 256 threads:
//   thread t -> (lane = t&127, j-half = t>>7). Each j-half team of 128
//   threads handles 8 of the 16 j's per tile.
// ---------------------------------------------------------------------------
__global__ void __launch_bounds__(TPB, 3) se3_main_kernel(
    const float* __restrict__ node_v,
    const float* __restrict__ rbf,
    const float* __restrict__ r_hat,
    const float* __restrict__ mask,
    const float* __restrict__ w1_0, const float* __restrict__ b1_0,
    const float* __restrict__ w2_0, const float* __restrict__ b2_0,
    const float* __restrict__ w1_1, const float* __restrict__ b1_1,
    const float* __restrict__ w2_1, const float* __restrict__ b2_1,
    const float* __restrict__ w1_2, const float* __restrict__ b1_2,
    const float* __restrict__ w2_2, const float* __restrict__ b2_2,
    const float* __restrict__ w1_3, const float* __restrict__ b1_3,
    const float* __restrict__ w2_3, const float* __restrict__ b2_3,
    const float* __restrict__ ln_g, const float* __restrict__ ln_b,
    const float* __restrict__ out_w, const float* __restrict__ out_b,
    const float* __restrict__ v_scale, const float* __restrict__ t_scale,
    float* __restrict__ out) {

    __shared__ float sh_s[DD * SSTRIDE];     // [e][j][k0..3] (+pad)
    __shared__ float sh_rbfT[RR][JT];        // [r][j]
    __shared__ float sh_Y1[3][JT];
    __shared__ float sh_Y2[5][JT];
    __shared__ float sh_mask[JT];
    __shared__ float sh_part[10][DD];        // second-half partial accumulators
    __shared__ float sh_red[DD];
    __shared__ float sh_r1[4], sh_r2[4];

    const int tid   = threadIdx.x;
    const int lane  = tid & (DD - 1);        // = e in phase1, = d in phase2
    const int jh    = tid >> 7;              // 0 or 1
    const int jbase = jh * 8;
    const int bi    = blockIdx.x;
    const int b     = bi >> 8;
    const long long edge_base = (long long)bi * NN;

    const float* W1[4] = {w1_0, w1_1, w1_2, w1_3};
    const float* W2[4] = {w2_0, w2_1, w2_2, w2_3};

    float b1r[4];
    b1r[0] = b1_0[lane]; b1r[1] = b1_1[lane];
    b1r[2] = b1_2[lane]; b1r[3] = b1_3[lane];
    const ull bA = pack2(b2_0[lane], b2_1[lane]);   // branch pair (0,1)
    const ull bB = pack2(b2_2[lane], b2_3[lane]);   // branch pair (2,3)

    float vreg[3];
#pragma unroll
    for (int c = 0; c < 3; ++c)
        vreg[c] = node_v[((long long)bi * 3 + c) * DD + lane];

    float accS = 0.0f, accSV = 0.0f;
    float accV[3] = {0.0f, 0.0f, 0.0f};
    float accT[5] = {0.0f, 0.0f, 0.0f, 0.0f, 0.0f};

    for (int t = 0; t < NTILES; ++t) {
        const int j0 = t * JT;

        // ---- stage rbf (transposed), mask, Y1, Y2 ----
        for (int idx = tid; idx < JT * RR; idx += TPB) {
            int j = idx >> 5, r = idx & 31;
            sh_rbfT[r][j] = rbf[(edge_base + j0 + j) * RR + r];
        }
        if (tid < JT) {
            int j = tid;
            long long e = edge_base + j0 + j;
            sh_mask[j] = mask[e];
            float x = r_hat[e * 3 + 0];
            float y = r_hat[e * 3 + 1];
            float z = r_hat[e * 3 + 2];
            const float s3  = 1.7320508075688772f;
            const float c15 = 3.872983346207417f;
            const float c5h = 1.118033988749895f;
            sh_Y1[0][j] = s3 * x;
            sh_Y1[1][j] = s3 * y;
            sh_Y1[2][j] = s3 * z;
            sh_Y2[0][j] = c15 * x * y;
            sh_Y2[1][j] = c15 * y * z;
            sh_Y2[2][j] = c5h * (3.0f * z * z - 1.0f);
            sh_Y2[3][j] = c15 * x * z;
            sh_Y2[4][j] = 0.5f * c15 * (x * x - y * y);
        }
        __syncthreads();

        // ---- phase 1: hidden layer + SiLU. e = lane, 8 j's of this half ----
        {
            const int e = lane;
            ull h1[4][4];   // [k][j-pair]
#pragma unroll
            for (int k = 0; k < 4; ++k) {
                ull bd = pack2(b1r[k], b1r[k]);
#pragma unroll
                for (int p = 0; p < 4; ++p) h1[k][p] = bd;
            }
#pragma unroll 4
            for (int r = 0; r < RR; ++r) {
                const float4* rb4 =
                    reinterpret_cast<const float4*>(&sh_rbfT[r][jbase]);
                float4 f0 = rb4[0], f1 = rb4[1];
                ull r01 = pack2(f0.x, f0.y), r23 = pack2(f0.z, f0.w);
                ull r45 = pack2(f1.x, f1.y), r67 = pack2(f1.z, f1.w);
#pragma unroll
                for (int k = 0; k < 4; ++k) {
                    float w = W1[k][r * DD + e];
                    ull wd = pack2(w, w);
                    h1[k][0] = fma2(r01, wd, h1[k][0]);
                    h1[k][1] = fma2(r23, wd, h1[k][1]);
                    h1[k][2] = fma2(r45, wd, h1[k][2]);
                    h1[k][3] = fma2(r67, wd, h1[k][3]);
                }
            }
            float* srow = &sh_s[e * SSTRIDE];
#pragma unroll
            for (int p = 0; p < 4; ++p) {
                float2 v0 = unpack2(h1[0][p]);
                float2 v1 = unpack2(h1[1][p]);
                float2 v2 = unpack2(h1[2][p]);
                float2 v3 = unpack2(h1[3][p]);
                float4 se = make_float4(silu(v0.x), silu(v1.x), silu(v2.x), silu(v3.x));
                float4 so = make_float4(silu(v0.y), silu(v1.y), silu(v2.y), silu(v3.y));
                *reinterpret_cast<float4*>(&srow[(jbase + 2 * p) * 4])     = se;
                *reinterpret_cast<float4*>(&srow[(jbase + 2 * p + 1) * 4]) = so;
            }
        }
        __syncthreads();

        // ---- phase 2: second linear layer. d = lane, 8 j's of this half ----
        ull accA[8], accB[8];   // per j: (k0,k1) and (k2,k3) packed
#pragma unroll
        for (int j = 0; j < 8; ++j) { accA[j] = bA; accB[j] = bB; }

#pragma unroll 2
        for (int e = 0; e < DD; ++e) {
            float w0  = W2[0][e * DD + lane];
            float w1v = W2[1][e * DD + lane];
            float w2v = W2[2][e * DD + lane];
            float w3v = W2[3][e * DD + lane];
            ull wA = pack2(w0, w1v);
            ull wB = pack2(w2v, w3v);
            const float4* sp =
                reinterpret_cast<const float4*>(&sh_s[e * SSTRIDE + jbase * 4]);
#pragma unroll
            for (int j = 0; j < 8; ++j) {
                float4 sv = sp[j];                 // (k0,k1,k2,k3) for this (e,j)
                accA[j] = fma2(pack2(sv.x, sv.y), wA, accA[j]);
                accB[j] = fma2(pack2(sv.z, sv.w), wB, accB[j]);
            }
        }

        // ---- epilogue: fold mask, h_j, Y into running sums ----
#pragma unroll
        for (int j = 0; j < 8; ++j) {
            int jj = jbase + j;
            float2 rAB = unpack2(accA[j]);   // r0, r1
            float2 rCD = unpack2(accB[j]);   // r2, r3
            float m  = sh_mask[jj];
            float hj = g_h[((long long)b * NN + (j0 + jj)) * DD + lane];
            float mh = m * hj;
            accS = fmaf(mh, rAB.x, accS);
            float t1 = mh * rAB.y;
            float y10 = sh_Y1[0][jj], y11 = sh_Y1[1][jj], y12 = sh_Y1[2][jj];
            accV[0] = fmaf(t1, y10, accV[0]);
            accV[1] = fmaf(t1, y11, accV[1]);
            accV[2] = fmaf(t1, y12, accV[2]);
            float t2 = mh * rCD.x;
#pragma unroll
            for (int c = 0; c < 5; ++c)
                accT[c] = fmaf(t2, sh_Y2[c][jj], accT[c]);
            float dv = vreg[0] * y10 + vreg[1] * y11 + vreg[2] * y12;
            accSV = fmaf(m * dv, rCD.y, accSV);
        }
        __syncthreads();
    }

    // ---- combine the two j-half teams ----
    if (jh == 1) {
        sh_part[0][lane] = accS;
        sh_part[1][lane] = accV[0];
        sh_part[2][lane] = accV[1];
        sh_part[3][lane] = accV[2];
        sh_part[4][lane] = accT[0];
        sh_part[5][lane] = accT[1];
        sh_part[6][lane] = accT[2];
        sh_part[7][lane] = accT[3];
        sh_part[8][lane] = accT[4];
        sh_part[9][lane] = accSV;
    }
    __syncthreads();

    if (jh == 0) {
        accS    += sh_part[0][lane];
        accV[0] += sh_part[1][lane];
        accV[1] += sh_part[2][lane];
        accV[2] += sh_part[3][lane];
        accT[0] += sh_part[4][lane];
        accT[1] += sh_part[5][lane];
        accT[2] += sh_part[6][lane];
        accT[3] += sh_part[7][lane];
        accT[4] += sh_part[8][lane];
        accSV   += sh_part[9][lane];

        float x = accS + accSV;
        float s1 = x, s2 = x * x;
#pragma unroll
        for (int o = 16; o > 0; o >>= 1) {
            s1 += __shfl_xor_sync(0xffffffff, s1, o);
            s2 += __shfl_xor_sync(0xffffffff, s2, o);
        }
        if ((lane & 31) == 0) {
            sh_r1[lane >> 5] = s1;
            sh_r2[lane >> 5] = s2;
        }
    }
    __syncthreads();

    if (jh == 0) {
        float x = accS + accSV;
        float s1 = sh_r1[0] + sh_r1[1] + sh_r1[2] + sh_r1[3];
        float s2 = sh_r2[0] + sh_r2[1] + sh_r2[2] + sh_r2[3];
        float mean = s1 * (1.0f / DD);
        float var  = s2 * (1.0f / DD) - mean * mean;
        float nv = (x - mean) * rsqrtf(var + 1e-5f) * ln_g[lane] + ln_b[lane];
        sh_red[lane] = nv;
    }
    __syncthreads();

    if (jh == 0) {
        float y = out_b[lane];
#pragma unroll 8
        for (int e = 0; e < DD; ++e)
            y = fmaf(sh_red[e], out_w[e * DD + lane], y);

        const long long VOFF = (long long)BB * NN * DD;
        const long long TOFF = VOFF + (long long)BB * NN * 3 * DD;

        out[(long long)bi * DD + lane] = y;
        float vs = v_scale[lane];
#pragma unroll
        for (int c = 0; c < 3; ++c)
            out[VOFF + ((long long)bi * 3 + c) * DD + lane] = accV[c] * vs;
        float ts = t_scale[lane];
#pragma unroll
        for (int c = 0; c < 5; ++c)
            out[TOFF + ((long long)bi * 5 + c) * DD + lane] = accT[c] * ts;
    }
}

// ---------------------------------------------------------------------------
// kernel_launch
// ---------------------------------------------------------------------------
extern "C" void kernel_launch(void* const* d_in, const int* in_sizes, int n_in,
                              void* d_out, int out_size) {
    const float* node_s  = (const float*)d_in[0];
    const float* node_v  = (const float*)d_in[1];
    const float* rbf     = (const float*)d_in[3];
    const float* r_hat   = (const float*)d_in[4];
    const float* mask    = (const float*)d_in[5];
    const float* r0_w1   = (const float*)d_in[6];
    const float* r0_b1   = (const float*)d_in[7];
    const float* r0_w2   = (const float*)d_in[8];
    const float* r0_b2   = (const float*)d_in[9];
    const float* r1_w1   = (const float*)d_in[10];
    const float* r1_b1   = (const float*)d_in[11];
    const float* r1_w2   = (const float*)d_in[12];
    const float* r1_b2   = (const float*)d_in[13];
    const float* r2_w1   = (const float*)d_in[14];
    const float* r2_b1   = (const float*)d_in[15];
    const float* r2_w2   = (const float*)d_in[16];
    const float* r2_b2   = (const float*)d_in[17];
    const float* r110_w1 = (const float*)d_in[18];
    const float* r110_b1 = (const float*)d_in[19];
    const float* r110_w2 = (const float*)d_in[20];
    const float* r110_b2 = (const float*)d_in[21];
    const float* src_w   = (const float*)d_in[22];
    const float* ln_g    = (const float*)d_in[23];
    const float* ln_b    = (const float*)d_in[24];
    const float* out_w   = (const float*)d_in[25];
    const float* out_b   = (const float*)d_in[26];
    const float* v_scale = (const float*)d_in[27];
    const float* t_scale = (const float*)d_in[28];

    float* out = (float*)d_out;

    compute_h_kernel<<<BB * NN, DD>>>(node_s, src_w);
    se3_main_kernel<<<BB * NN, TPB>>>(
        node_v, rbf, r_hat, mask,
        r0_w1, r0_b1, r0_w2, r0_b2,
        r1_w1, r1_b1, r1_w2, r1_b2,
        r2_w1, r2_b1, r2_w2, r2_b2,
        r110_w1, r110_b1, r110_w2, r110_b2,
        ln_g, ln_b, out_w, out_b, v_scale, t_scale, out);
}

// round 8
// speedup vs baseline: 1.0010x; 1.0006x over previous
#include <cuda_runtime.h>

#define BB 2
#define NN 256
#define DD 128
#define RR 32
#define JT 16
#define NTILES (NN / JT)
#define TPB 256
#define SSTRIDE 68   // floats per e-row in sh_s: 16 j * 4 k + 4 pad (16B-aligned)

typedef unsigned long long ull;

// scratch for h = node_s @ src_w  (B*N*D floats)
__device__ float g_h[BB * NN * DD];

// ---------------------------------------------------------------------------
// packed f32x2 helpers
// ---------------------------------------------------------------------------
__device__ __forceinline__ ull pack2(float lo, float hi) {
    ull r;
    asm("mov.b64 %0, {%1, %2};" : "=l"(r) : "f"(lo), "f"(hi));
    return r;
}
__device__ __forceinline__ float2 unpack2(ull v) {
    float2 f;
    asm("mov.b64 {%0, %1}, %2;" : "=f"(f.x), "=f"(f.y) : "l"(v));
    return f;
}
__device__ __forceinline__ ull fma2(ull a, ull b, ull c) {
    ull d;
    asm("fma.rn.f32x2 %0, %1, %2, %3;" : "=l"(d) : "l"(a), "l"(b), "l"(c));
    return d;
}
__device__ __forceinline__ float silu(float x) {
    return x / (1.0f + __expf(-x));
}

// ---------------------------------------------------------------------------
// Kernel 1: h[b,n,d] = node_s[b,n,:] @ src_w[:,d]
// ---------------------------------------------------------------------------
__global__ void __launch_bounds__(DD) compute_h_kernel(
    const float* __restrict__ node_s,
    const float* __restrict__ src_w) {
    __shared__ float sh[DD];
    int row = blockIdx.x;
    int d = threadIdx.x;
    sh[d] = node_s[row * DD + d];
    __syncthreads();
    float acc = 0.0f;
#pragma unroll 8
    for (int k = 0; k < DD; ++k)
        acc = fmaf(sh[k], src_w[k * DD + d], acc);
    g_h[row * DD + d] = acc;
}

// ---------------------------------------------------------------------------
// Kernel 2: fused message block. One CTA per (b,i); 256 threads:
//   thread t -> (lane = t&127, j-half = t>>7). Each j-half team of 128
//   threads handles 8 of the 16 j's per tile.
// ---------------------------------------------------------------------------
__global__ void __launch_bounds__(TPB, 3) se3_main_kernel(
    const float* __restrict__ node_v,
    const float* __restrict__ rbf,
    const float* __restrict__ r_hat,
    const float* __restrict__ mask,
    const float* __restrict__ w1_0, const float* __restrict__ b1_0,
    const float* __restrict__ w2_0, const float* __restrict__ b2_0,
    const float* __restrict__ w1_1, const float* __restrict__ b1_1,
    const float* __restrict__ w2_1, const float* __restrict__ b2_1,
    const float* __restrict__ w1_2, const float* __restrict__ b1_2,
    const float* __restrict__ w2_2, const float* __restrict__ b2_2,
    const float* __restrict__ w1_3, const float* __restrict__ b1_3,
    const float* __restrict__ w2_3, const float* __restrict__ b2_3,
    const float* __restrict__ ln_g, const float* __restrict__ ln_b,
    const float* __restrict__ out_w, const float* __restrict__ out_b,
    const float* __restrict__ v_scale, const float* __restrict__ t_scale,
    float* __restrict__ out) {

    __shared__ float sh_s[DD * SSTRIDE];     // [e][j][k0..3] (+pad)
    __shared__ float sh_rbfT[RR][JT];        // [r][j]
    __shared__ float sh_Y1[3][JT];
    __shared__ float sh_Y2[5][JT];
    __shared__ float sh_mask[JT];
    __shared__ float sh_part[10][DD];        // second-half partial accumulators
    __shared__ float sh_red[DD];
    __shared__ float sh_r1[4], sh_r2[4];

    const int tid   = threadIdx.x;
    const int lane  = tid & (DD - 1);        // = e in phase1, = d in phase2
    const int jh    = tid >> 7;              // 0 or 1
    const int jbase = jh * 8;
    const int bi    = blockIdx.x;
    const int b     = bi >> 8;
    const long long edge_base = (long long)bi * NN;

    const float* W1[4] = {w1_0, w1_1, w1_2, w1_3};
    const float* W2[4] = {w2_0, w2_1, w2_2, w2_3};

    float b1r[4];
    b1r[0] = b1_0[lane]; b1r[1] = b1_1[lane];
    b1r[2] = b1_2[lane]; b1r[3] = b1_3[lane];
    const ull bA = pack2(b2_0[lane], b2_1[lane]);   // branch pair (0,1)
    const ull bB = pack2(b2_2[lane], b2_3[lane]);   // branch pair (2,3)

    float vreg[3];
#pragma unroll
    for (int c = 0; c < 3; ++c)
        vreg[c] = node_v[((long long)bi * 3 + c) * DD + lane];

    float accS = 0.0f, accSV = 0.0f;
    float accV[3] = {0.0f, 0.0f, 0.0f};
    float accT[5] = {0.0f, 0.0f, 0.0f, 0.0f, 0.0f};

    for (int t = 0; t < NTILES; ++t) {
        const int j0 = t * JT;

        // ---- stage rbf (transposed), mask, Y1, Y2 ----
        for (int idx = tid; idx < JT * RR; idx += TPB) {
            int j = idx >> 5, r = idx & 31;
            sh_rbfT[r][j] = rbf[(edge_base + j0 + j) * RR + r];
        }
        if (tid < JT) {
            int j = tid;
            long long e = edge_base + j0 + j;
            sh_mask[j] = mask[e];
            float x = r_hat[e * 3 + 0];
            float y = r_hat[e * 3 + 1];
            float z = r_hat[e * 3 + 2];
            const float s3  = 1.7320508075688772f;
            const float c15 = 3.872983346207417f;
            const float c5h = 1.118033988749895f;
            sh_Y1[0][j] = s3 * x;
            sh_Y1[1][j] = s3 * y;
            sh_Y1[2][j] = s3 * z;
            sh_Y2[0][j] = c15 * x * y;
            sh_Y2[1][j] = c15 * y * z;
            sh_Y2[2][j] = c5h * (3.0f * z * z - 1.0f);
            sh_Y2[3][j] = c15 * x * z;
            sh_Y2[4][j] = 0.5f * c15 * (x * x - y * y);
        }
        __syncthreads();

        // ---- phase 1: hidden layer + SiLU. e = lane, 8 j's of this half ----
        {
            const int e = lane;
            ull h1[4][4];   // [k][j-pair]
#pragma unroll
            for (int k = 0; k < 4; ++k) {
                ull bd = pack2(b1r[k], b1r[k]);
#pragma unroll
                for (int p = 0; p < 4; ++p) h1[k][p] = bd;
            }
#pragma unroll 4
            for (int r = 0; r < RR; ++r) {
                const float4* rb4 =
                    reinterpret_cast<const float4*>(&sh_rbfT[r][jbase]);
                float4 f0 = rb4[0], f1 = rb4[1];
                ull r01 = pack2(f0.x, f0.y), r23 = pack2(f0.z, f0.w);
                ull r45 = pack2(f1.x, f1.y), r67 = pack2(f1.z, f1.w);
#pragma unroll
                for (int k = 0; k < 4; ++k) {
                    float w = W1[k][r * DD + e];
                    ull wd = pack2(w, w);
                    h1[k][0] = fma2(r01, wd, h1[k][0]);
                    h1[k][1] = fma2(r23, wd, h1[k][1]);
                    h1[k][2] = fma2(r45, wd, h1[k][2]);
                    h1[k][3] = fma2(r67, wd, h1[k][3]);
                }
            }
            float* srow = &sh_s[e * SSTRIDE];
#pragma unroll
            for (int p = 0; p < 4; ++p) {
                float2 v0 = unpack2(h1[0][p]);
                float2 v1 = unpack2(h1[1][p]);
                float2 v2 = unpack2(h1[2][p]);
                float2 v3 = unpack2(h1[3][p]);
                float4 se = make_float4(silu(v0.x), silu(v1.x), silu(v2.x), silu(v3.x));
                float4 so = make_float4(silu(v0.y), silu(v1.y), silu(v2.y), silu(v3.y));
                *reinterpret_cast<float4*>(&srow[(jbase + 2 * p) * 4])     = se;
                *reinterpret_cast<float4*>(&srow[(jbase + 2 * p + 1) * 4]) = so;
            }
        }
        __syncthreads();

        // ---- phase 2: second linear layer. d = lane, 8 j's of this half ----
        ull accA[8], accB[8];   // per j: (k0,k1) and (k2,k3) packed
#pragma unroll
        for (int j = 0; j < 8; ++j) { accA[j] = bA; accB[j] = bB; }

#pragma unroll 2
        for (int e = 0; e < DD; ++e) {
            float w0  = W2[0][e * DD + lane];
            float w1v = W2[1][e * DD + lane];
            float w2v = W2[2][e * DD + lane];
            float w3v = W2[3][e * DD + lane];
            ull wA = pack2(w0, w1v);
            ull wB = pack2(w2v, w3v);
            const float4* sp =
                reinterpret_cast<const float4*>(&sh_s[e * SSTRIDE + jbase * 4]);
#pragma unroll
            for (int j = 0; j < 8; ++j) {
                float4 sv = sp[j];                 // (k0,k1,k2,k3) for this (e,j)
                accA[j] = fma2(pack2(sv.x, sv.y), wA, accA[j]);
                accB[j] = fma2(pack2(sv.z, sv.w), wB, accB[j]);
            }
        }

        // ---- epilogue: fold mask, h_j, Y into running sums ----
#pragma unroll
        for (int j = 0; j < 8; ++j) {
            int jj = jbase + j;
            float2 rAB = unpack2(accA[j]);   // r0, r1
            float2 rCD = unpack2(accB[j]);   // r2, r3
            float m  = sh_mask[jj];
            float hj = g_h[((long long)b * NN + (j0 + jj)) * DD + lane];
            float mh = m * hj;
            accS = fmaf(mh, rAB.x, accS);
            float t1 = mh * rAB.y;
            float y10 = sh_Y1[0][jj], y11 = sh_Y1[1][jj], y12 = sh_Y1[2][jj];
            accV[0] = fmaf(t1, y10, accV[0]);
            accV[1] = fmaf(t1, y11, accV[1]);
            accV[2] = fmaf(t1, y12, accV[2]);
            float t2 = mh * rCD.x;
#pragma unroll
            for (int c = 0; c < 5; ++c)
                accT[c] = fmaf(t2, sh_Y2[c][jj], accT[c]);
            float dv = vreg[0] * y10 + vreg[1] * y11 + vreg[2] * y12;
            accSV = fmaf(m * dv, rCD.y, accSV);
        }
        __syncthreads();
    }

    // ---- combine the two j-half teams ----
    if (jh == 1) {
        sh_part[0][lane] = accS;
        sh_part[1][lane] = accV[0];
        sh_part[2][lane] = accV[1];
        sh_part[3][lane] = accV[2];
        sh_part[4][lane] = accT[0];
        sh_part[5][lane] = accT[1];
        sh_part[6][lane] = accT[2];
        sh_part[7][lane] = accT[3];
        sh_part[8][lane] = accT[4];
        sh_part[9][lane] = accSV;
    }
    __syncthreads();

    if (jh == 0) {
        accS    += sh_part[0][lane];
        accV[0] += sh_part[1][lane];
        accV[1] += sh_part[2][lane];
        accV[2] += sh_part[3][lane];
        accT[0] += sh_part[4][lane];
        accT[1] += sh_part[5][lane];
        accT[2] += sh_part[6][lane];
        accT[3] += sh_part[7][lane];
        accT[4] += sh_part[8][lane];
        accSV   += sh_part[9][lane];

        float x = accS + accSV;
        float s1 = x, s2 = x * x;
#pragma unroll
        for (int o = 16; o > 0; o >>= 1) {
            s1 += __shfl_xor_sync(0xffffffff, s1, o);
            s2 += __shfl_xor_sync(0xffffffff, s2, o);
        }
        if ((lane & 31) == 0) {
            sh_r1[lane >> 5] = s1;
            sh_r2[lane >> 5] = s2;
        }
    }
    __syncthreads();

    if (jh == 0) {
        float x = accS + accSV;
        float s1 = sh_r1[0] + sh_r1[1] + sh_r1[2] + sh_r1[3];
        float s2 = sh_r2[0] + sh_r2[1] + sh_r2[2] + sh_r2[3];
        float mean = s1 * (1.0f / DD);
        float var  = s2 * (1.0f / DD) - mean * mean;
        float nv = (x - mean) * rsqrtf(var + 1e-5f) * ln_g[lane] + ln_b[lane];
        sh_red[lane] = nv;
    }
    __syncthreads();

    if (jh == 0) {
        float y = out_b[lane];
#pragma unroll 8
        for (int e = 0; e < DD; ++e)
            y = fmaf(sh_red[e], out_w[e * DD + lane], y);

        const long long VOFF = (long long)BB * NN * DD;
        const long long TOFF = VOFF + (long long)BB * NN * 3 * DD;

        out[(long long)bi * DD + lane] = y;
        float vs = v_scale[lane];
#pragma unroll
        for (int c = 0; c < 3; ++c)
            out[VOFF + ((long long)bi * 3 + c) * DD + lane] = accV[c] * vs;
        float ts = t_scale[lane];
#pragma unroll
        for (int c = 0; c < 5; ++c)
            out[TOFF + ((long long)bi * 5 + c) * DD + lane] = accT[c] * ts;
    }
}

// ---------------------------------------------------------------------------
// kernel_launch
// ---------------------------------------------------------------------------
extern "C" void kernel_launch(void* const* d_in, const int* in_sizes, int n_in,
                              void* d_out, int out_size) {
    const float* node_s  = (const float*)d_in[0];
    const float* node_v  = (const float*)d_in[1];
    const float* rbf     = (const float*)d_in[3];
    const float* r_hat   = (const float*)d_in[4];
    const float* mask    = (const float*)d_in[5];
    const float* r0_w1   = (const float*)d_in[6];
    const float* r0_b1   = (const float*)d_in[7];
    const float* r0_w2   = (const float*)d_in[8];
    const float* r0_b2   = (const float*)d_in[9];
    const float* r1_w1   = (const float*)d_in[10];
    const float* r1_b1   = (const float*)d_in[11];
    const float* r1_w2   = (const float*)d_in[12];
    const float* r1_b2   = (const float*)d_in[13];
    const float* r2_w1   = (const float*)d_in[14];
    const float* r2_b1   = (const float*)d_in[15];
    const float* r2_w2   = (const float*)d_in[16];
    const float* r2_b2   = (const float*)d_in[17];
    const float* r110_w1 = (const float*)d_in[18];
    const float* r110_b1 = (const float*)d_in[19];
    const float* r110_w2 = (const float*)d_in[20];
    const float* r110_b2 = (const float*)d_in[21];
    const float* src_w   = (const float*)d_in[22];
    const float* ln_g    = (const float*)d_in[23];
    const float* ln_b    = (const float*)d_in[24];
    const float* out_w   = (const float*)d_in[25];
    const float* out_b   = (const float*)d_in[26];
    const float* v_scale = (const float*)d_in[27];
    const float* t_scale = (const float*)d_in[28];

    float* out = (float*)d_out;

    compute_h_kernel<<<BB * NN, DD>>>(node_s, src_w);
    se3_main_kernel<<<BB * NN, TPB>>>(
        node_v, rbf, r_hat, mask,
        r0_w1, r0_b1, r0_w2, r0_b2,
        r1_w1, r1_b1, r1_w2, r1_b2,
        r2_w1, r2_b1, r2_w2, r2_b2,
        r110_w1, r110_b1, r110_w2, r110_b2,
        ln_g, ln_b, out_w, out_b, v_scale, t_scale, out);
}

// round 9
// speedup vs baseline: 1.0023x; 1.0013x over previous
#include <cuda_runtime.h>

#define BB 2
#define NN 256
#define DD 128
#define RR 32
#define JT 16
#define NTILES (NN / JT)
#define TPB 256
#define SSTRIDE 68   // floats per e-row in sh_s: 16 j * 4 k + 4 pad (16B-aligned)

typedef unsigned long long ull;

// scratch for h = node_s @ src_w  (B*N*D floats)
__device__ float g_h[BB * NN * DD];

// ---------------------------------------------------------------------------
// packed f32x2 helpers
// ---------------------------------------------------------------------------
__device__ __forceinline__ ull pack2(float lo, float hi) {
    ull r;
    asm("mov.b64 %0, {%1, %2};" : "=l"(r) : "f"(lo), "f"(hi));
    return r;
}
__device__ __forceinline__ float2 unpack2(ull v) {
    float2 f;
    asm("mov.b64 {%0, %1}, %2;" : "=f"(f.x), "=f"(f.y) : "l"(v));
    return f;
}
__device__ __forceinline__ ull fma2(ull a, ull b, ull c) {
    ull d;
    asm("fma.rn.f32x2 %0, %1, %2, %3;" : "=l"(d) : "l"(a), "l"(b), "l"(c));
    return d;
}
__device__ __forceinline__ float silu(float x) {
    return x / (1.0f + __expf(-x));
}

// ---------------------------------------------------------------------------
// Kernel 1: h[b,n,d] = node_s[b,n,:] @ src_w[:,d]
// ---------------------------------------------------------------------------
__global__ void __launch_bounds__(DD) compute_h_kernel(
    const float* __restrict__ node_s,
    const float* __restrict__ src_w) {
    __shared__ float sh[DD];
    int row = blockIdx.x;
    int d = threadIdx.x;
    sh[d] = node_s[row * DD + d];
    __syncthreads();
    float acc = 0.0f;
#pragma unroll 8
    for (int k = 0; k < DD; ++k)
        acc = fmaf(sh[k], src_w[k * DD + d], acc);
    g_h[row * DD + d] = acc;
}

// ---------------------------------------------------------------------------
// Kernel 2: fused message block. One CTA per (b,i); 256 threads:
//   thread t -> (lane = t&127, j-half = t>>7). Each j-half team of 128
//   threads handles 8 of the 16 j's per tile.
// ---------------------------------------------------------------------------
__global__ void __launch_bounds__(TPB, 3) se3_main_kernel(
    const float* __restrict__ node_v,
    const float* __restrict__ rbf,
    const float* __restrict__ r_hat,
    const float* __restrict__ mask,
    const float* __restrict__ w1_0, const float* __restrict__ b1_0,
    const float* __restrict__ w2_0, const float* __restrict__ b2_0,
    const float* __restrict__ w1_1, const float* __restrict__ b1_1,
    const float* __restrict__ w2_1, const float* __restrict__ b2_1,
    const float* __restrict__ w1_2, const float* __restrict__ b1_2,
    const float* __restrict__ w2_2, const float* __restrict__ b2_2,
    const float* __restrict__ w1_3, const float* __restrict__ b1_3,
    const float* __restrict__ w2_3, const float* __restrict__ b2_3,
    const float* __restrict__ ln_g, const float* __restrict__ ln_b,
    const float* __restrict__ out_w, const float* __restrict__ out_b,
    const float* __restrict__ v_scale, const float* __restrict__ t_scale,
    float* __restrict__ out) {

    __shared__ float sh_s[DD * SSTRIDE];     // [e][j][k0..3] (+pad)
    __shared__ float sh_rbfT[RR][JT];        // [r][j]
    __shared__ float sh_Y1[3][JT];
    __shared__ float sh_Y2[5][JT];
    __shared__ float sh_mask[JT];
    __shared__ float sh_part[10][DD];        // second-half partial accumulators
    __shared__ float sh_red[DD];
    __shared__ float sh_r1[4], sh_r2[4];

    const int tid   = threadIdx.x;
    const int lane  = tid & (DD - 1);        // = e in phase1, = d in phase2
    const int jh    = tid >> 7;              // 0 or 1
    const int jbase = jh * 8;
    const int bi    = blockIdx.x;
    const int b     = bi >> 8;
    const long long edge_base = (long long)bi * NN;

    const float* W1[4] = {w1_0, w1_1, w1_2, w1_3};
    const float* W2[4] = {w2_0, w2_1, w2_2, w2_3};

    float b1r[4];
    b1r[0] = b1_0[lane]; b1r[1] = b1_1[lane];
    b1r[2] = b1_2[lane]; b1r[3] = b1_3[lane];
    const ull bA = pack2(b2_0[lane], b2_1[lane]);   // branch pair (0,1)
    const ull bB = pack2(b2_2[lane], b2_3[lane]);   // branch pair (2,3)

    float vreg[3];
#pragma unroll
    for (int c = 0; c < 3; ++c)
        vreg[c] = node_v[((long long)bi * 3 + c) * DD + lane];

    float accS = 0.0f, accSV = 0.0f;
    float accV[3] = {0.0f, 0.0f, 0.0f};
    float accT[5] = {0.0f, 0.0f, 0.0f, 0.0f, 0.0f};

    for (int t = 0; t < NTILES; ++t) {
        const int j0 = t * JT;

        // ---- stage rbf (transposed), mask, Y1, Y2 ----
        for (int idx = tid; idx < JT * RR; idx += TPB) {
            int j = idx >> 5, r = idx & 31;
            sh_rbfT[r][j] = rbf[(edge_base + j0 + j) * RR + r];
        }
        if (tid < JT) {
            int j = tid;
            long long e = edge_base + j0 + j;
            sh_mask[j] = mask[e];
            float x = r_hat[e * 3 + 0];
            float y = r_hat[e * 3 + 1];
            float z = r_hat[e * 3 + 2];
            const float s3  = 1.7320508075688772f;
            const float c15 = 3.872983346207417f;
            const float c5h = 1.118033988749895f;
            sh_Y1[0][j] = s3 * x;
            sh_Y1[1][j] = s3 * y;
            sh_Y1[2][j] = s3 * z;
            sh_Y2[0][j] = c15 * x * y;
            sh_Y2[1][j] = c15 * y * z;
            sh_Y2[2][j] = c5h * (3.0f * z * z - 1.0f);
            sh_Y2[3][j] = c15 * x * z;
            sh_Y2[4][j] = 0.5f * c15 * (x * x - y * y);
        }
        __syncthreads();

        // ---- phase 1: hidden layer + SiLU. e = lane, 8 j's of this half ----
        {
            const int e = lane;
            ull h1[4][4];   // [k][j-pair]
#pragma unroll
            for (int k = 0; k < 4; ++k) {
                ull bd = pack2(b1r[k], b1r[k]);
#pragma unroll
                for (int p = 0; p < 4; ++p) h1[k][p] = bd;
            }
#pragma unroll 4
            for (int r = 0; r < RR; ++r) {
                const float4* rb4 =
                    reinterpret_cast<const float4*>(&sh_rbfT[r][jbase]);
                float4 f0 = rb4[0], f1 = rb4[1];
                ull r01 = pack2(f0.x, f0.y), r23 = pack2(f0.z, f0.w);
                ull r45 = pack2(f1.x, f1.y), r67 = pack2(f1.z, f1.w);
#pragma unroll
                for (int k = 0; k < 4; ++k) {
                    float w = W1[k][r * DD + e];
                    ull wd = pack2(w, w);
                    h1[k][0] = fma2(r01, wd, h1[k][0]);
                    h1[k][1] = fma2(r23, wd, h1[k][1]);
                    h1[k][2] = fma2(r45, wd, h1[k][2]);
                    h1[k][3] = fma2(r67, wd, h1[k][3]);
                }
            }
            float* srow = &sh_s[e * SSTRIDE];
#pragma unroll
            for (int p = 0; p < 4; ++p) {
                float2 v0 = unpack2(h1[0][p]);
                float2 v1 = unpack2(h1[1][p]);
                float2 v2 = unpack2(h1[2][p]);
                float2 v3 = unpack2(h1[3][p]);
                float4 se = make_float4(silu(v0.x), silu(v1.x), silu(v2.x), silu(v3.x));
                float4 so = make_float4(silu(v0.y), silu(v1.y), silu(v2.y), silu(v3.y));
                *reinterpret_cast<float4*>(&srow[(jbase + 2 * p) * 4])     = se;
                *reinterpret_cast<float4*>(&srow[(jbase + 2 * p + 1) * 4]) = so;
            }
        }
        __syncthreads();

        // ---- phase 2: second linear layer. d = lane, 8 j's of this half ----
        ull accA[8], accB[8];   // per j: (k0,k1) and (k2,k3) packed
#pragma unroll
        for (int j = 0; j < 8; ++j) { accA[j] = bA; accB[j] = bB; }

#pragma unroll 2
        for (int e = 0; e < DD; ++e) {
            float w0  = W2[0][e * DD + lane];
            float w1v = W2[1][e * DD + lane];
            float w2v = W2[2][e * DD + lane];
            float w3v = W2[3][e * DD + lane];
            ull wA = pack2(w0, w1v);
            ull wB = pack2(w2v, w3v);
            const float4* sp =
                reinterpret_cast<const float4*>(&sh_s[e * SSTRIDE + jbase * 4]);
#pragma unroll
            for (int j = 0; j < 8; ++j) {
                float4 sv = sp[j];                 // (k0,k1,k2,k3) for this (e,j)
                accA[j] = fma2(pack2(sv.x, sv.y), wA, accA[j]);
                accB[j] = fma2(pack2(sv.z, sv.w), wB, accB[j]);
            }
        }

        // ---- epilogue: fold mask, h_j, Y into running sums ----
#pragma unroll
        for (int j = 0; j < 8; ++j) {
            int jj = jbase + j;
            float2 rAB = unpack2(accA[j]);   // r0, r1
            float2 rCD = unpack2(accB[j]);   // r2, r3
            float m  = sh_mask[jj];
            float hj = g_h[((long long)b * NN + (j0 + jj)) * DD + lane];
            float mh = m * hj;
            accS = fmaf(mh, rAB.x, accS);
            float t1 = mh * rAB.y;
            float y10 = sh_Y1[0][jj], y11 = sh_Y1[1][jj], y12 = sh_Y1[2][jj];
            accV[0] = fmaf(t1, y10, accV[0]);
            accV[1] = fmaf(t1, y11, accV[1]);
            accV[2] = fmaf(t1, y12, accV[2]);
            float t2 = mh * rCD.x;
#pragma unroll
            for (int c = 0; c < 5; ++c)
                accT[c] = fmaf(t2, sh_Y2[c][jj], accT[c]);
            float dv = vreg[0] * y10 + vreg[1] * y11 + vreg[2] * y12;
            accSV = fmaf(m * dv, rCD.y, accSV);
        }
        __syncthreads();
    }

    // ---- combine the two j-half teams ----
    if (jh == 1) {
        sh_part[0][lane] = accS;
        sh_part[1][lane] = accV[0];
        sh_part[2][lane] = accV[1];
        sh_part[3][lane] = accV[2];
        sh_part[4][lane] = accT[0];
        sh_part[5][lane] = accT[1];
        sh_part[6][lane] = accT[2];
        sh_part[7][lane] = accT[3];
        sh_part[8][lane] = accT[4];
        sh_part[9][lane] = accSV;
    }
    __syncthreads();

    if (jh == 0) {
        accS    += sh_part[0][lane];
        accV[0] += sh_part[1][lane];
        accV[1] += sh_part[2][lane];
        accV[2] += sh_part[3][lane];
        accT[0] += sh_part[4][lane];
        accT[1] += sh_part[5][lane];
        accT[2] += sh_part[6][lane];
        accT[3] += sh_part[7][lane];
        accT[4] += sh_part[8][lane];
        accSV   += sh_part[9][lane];

        float x = accS + accSV;
        float s1 = x, s2 = x * x;
#pragma unroll
        for (int o = 16; o > 0; o >>= 1) {
            s1 += __shfl_xor_sync(0xffffffff, s1, o);
            s2 += __shfl_xor_sync(0xffffffff, s2, o);
        }
        if ((lane & 31) == 0) {
            sh_r1[lane >> 5] = s1;
            sh_r2[lane >> 5] = s2;
        }
    }
    __syncthreads();

    if (jh == 0) {
        float x = accS + accSV;
        float s1 = sh_r1[0] + sh_r1[1] + sh_r1[2] + sh_r1[3];
        float s2 = sh_r2[0] + sh_r2[1] + sh_r2[2] + sh_r2[3];
        float mean = s1 * (1.0f / DD);
        float var  = s2 * (1.0f / DD) - mean * mean;
        float nv = (x - mean) * rsqrtf(var + 1e-5f) * ln_g[lane] + ln_b[lane];
        sh_red[lane] = nv;
    }
    __syncthreads();

    if (jh == 0) {
        float y = out_b[lane];
#pragma unroll 8
        for (int e = 0; e < DD; ++e)
            y = fmaf(sh_red[e], out_w[e * DD + lane], y);

        const long long VOFF = (long long)BB * NN * DD;
        const long long TOFF = VOFF + (long long)BB * NN * 3 * DD;

        out[(long long)bi * DD + lane] = y;
        float vs = v_scale[lane];
#pragma unroll
        for (int c = 0; c < 3; ++c)
            out[VOFF + ((long long)bi * 3 + c) * DD + lane] = accV[c] * vs;
        float ts = t_scale[lane];
#pragma unroll
        for (int c = 0; c < 5; ++c)
            out[TOFF + ((long long)bi * 5 + c) * DD + lane] = accT[c] * ts;
    }
}

// ---------------------------------------------------------------------------
// kernel_launch
// ---------------------------------------------------------------------------
extern "C" void kernel_launch(void* const* d_in, const int* in_sizes, int n_in,
                              void* d_out, int out_size) {
    const float* node_s  = (const float*)d_in[0];
    const float* node_v  = (const float*)d_in[1];
    const float* rbf     = (const float*)d_in[3];
    const float* r_hat   = (const float*)d_in[4];
    const float* mask    = (const float*)d_in[5];
    const float* r0_w1   = (const float*)d_in[6];
    const float* r0_b1   = (const float*)d_in[7];
    const float* r0_w2   = (const float*)d_in[8];
    const float* r0_b2   = (const float*)d_in[9];
    const float* r1_w1   = (const float*)d_in[10];
    const float* r1_b1   = (const float*)d_in[11];
    const float* r1_w2   = (const float*)d_in[12];
    const float* r1_b2   = (const float*)d_in[13];
    const float* r2_w1   = (const float*)d_in[14];
    const float* r2_b1   = (const float*)d_in[15];
    const float* r2_w2   = (const float*)d_in[16];
    const float* r2_b2   = (const float*)d_in[17];
    const float* r110_w1 = (const float*)d_in[18];
    const float* r110_b1 = (const float*)d_in[19];
    const float* r110_w2 = (const float*)d_in[20];
    const float* r110_b2 = (const float*)d_in[21];
    const float* src_w   = (const float*)d_in[22];
    const float* ln_g    = (const float*)d_in[23];
    const float* ln_b    = (const float*)d_in[24];
    const float* out_w   = (const float*)d_in[25];
    const float* out_b   = (const float*)d_in[26];
    const float* v_scale = (const float*)d_in[27];
    const float* t_scale = (const float*)d_in[28];

    float* out = (float*)d_out;

    compute_h_kernel<<<BB * NN, DD>>>(node_s, src_w);
    se3_main_kernel<<<BB * NN, TPB>>>(
        node_v, rbf, r_hat, mask,
        r0_w1, r0_b1, r0_w2, r0_b2,
        r1_w1, r1_b1, r1_w2, r1_b2,
        r2_w1, r2_b1, r2_w2, r2_b2,
        r110_w1, r110_b1, r110_w2, r110_b2,
        ln_g, ln_b, out_w, out_b, v_scale, t_scale, out);
}